// round 16
// baseline (speedup 1.0000x reference)
#include <cuda_runtime.h>
#include <cuda_fp16.h>
#include <cstdint>
#include <cstddef>

// Problem constants
#define B_  4
#define S_  1024
#define D_  1024
#define F_  4096
#define M_  512
#define H_  16
#define HD_ 64
#define L_  2
#define N_  (B_ * S_)   // 4096 tokens
#define RL_ 3072        // fused local rows (2048 + 1024)

// ---------------------------------------------------------------------------
// Scratch buffers (static device globals; no runtime allocation)
// ---------------------------------------------------------------------------
__device__ float g_g [N_ * D_];
__device__ float g_q [N_ * D_];        // generic fp32 delta scratch
__device__ float g_xs [RL_ * D_];
__device__ float g_mo [RL_ * D_];
__device__ float g_y24[RL_ * D_];
__device__ float g_h [N_ * D_];
// fp16 shadow activations (GEMM A inputs)
__device__ __half h_g [N_ * D_];
__device__ __half h_os[N_ * D_];
__device__ __half h_ao[N_ * D_];
__device__ __half h_xs[RL_ * D_];
__device__ __half h_mid[RL_ * M_];
__device__ __half h_ff[N_ * F_];
__device__ __half h_qkv[N_ * 3 * D_];
// fp16 weight copies (PERMUTED half2 block layout)
__device__ uint32_t t_Wqkv[L_ * D_ * 3 * D_ / 2];
__device__ float    b_qkv [L_ * 3 * D_];
__device__ uint32_t t_Wo [L_ * D_ * D_ / 2];
__device__ uint32_t t_W1 [L_ * D_ * F_ / 2];
__device__ uint32_t t_W2 [L_ * F_ * D_ / 2];
__device__ uint32_t t_Wb [D_ * M_ / 2];
__device__ uint32_t t_Wm [M_ * D_ / 2];
__device__ uint32_t t_Wf1[D_ * F_ / 2];
__device__ uint32_t t_Wf2[F_ * D_ / 2];

// ---------------------------------------------------------------------------
__device__ __forceinline__ uint32_t pack_h2(float a, float b) {
    __half2 h = __floats2half2_rn(a, b);
    return *(uint32_t*)&h;
}

__device__ __forceinline__ void cp16(uint32_t dst_smem, const void* src) {
    asm volatile("cp.async.cg.shared.global [%0], [%1], 16;\n" :: "r"(dst_smem), "l"(src));
}

// Permuted block layout (uint = half2 pair of adjacent k).
// Block = [32 k][256 n] = [16 kpairs][256 n] = 4096 uints, contiguous.
__device__ __forceinline__ int wperm_addr(int kp, int nl) {
    int s = kp >> 3, t4 = kp & 3, hik = (kp >> 2) & 1;
    int ng = nl >> 4, cc = nl & 15, jj2 = cc >> 3, gg = cc & 7;
    return (((s * 16 + ng) * 32) + gg * 4 + t4) * 4 + hik + 2 * jj2;
}

// fp32 [K][N] -> permuted fp16 blocks.
__global__ __launch_bounds__(256) void cvtwp_kernel(const float4* __restrict__ in,
                                                    uint32_t* __restrict__ out,
                                                    int K, int N) {
    int i = blockIdx.x * 256 + threadIdx.x;
    int n4 = N >> 2;
    if (i >= (K >> 1) * n4) return;
    int kp_g = i / n4;
    int n0 = (i % n4) << 2;
    float4 lo = in[(size_t)(2 * kp_g) * n4 + (n0 >> 2)];
    float4 hi = in[(size_t)(2 * kp_g + 1) * n4 + (n0 >> 2)];
    int kt = kp_g >> 4, kp = kp_g & 15;
    int bx = n0 >> 8;
    int nkt = K >> 5;
    uint32_t* blk = out + ((size_t)bx * nkt + kt) * 4096;
    float flo[4] = {lo.x, lo.y, lo.z, lo.w};
    float fhi[4] = {hi.x, hi.y, hi.z, hi.w};
#pragma unroll
    for (int j = 0; j < 4; j++)
        blk[wperm_addr(kp, (n0 & 255) + j)] = pack_h2(flo[j], fhi[j]);
}

// Pack Wq|Wk|Wv (one layer) into [1024][3072] permuted fp16 blocks
__global__ __launch_bounds__(256) void cvtwp_qkv_kernel(const float4* __restrict__ wq,
                                                        const float4* __restrict__ wk,
                                                        const float4* __restrict__ wv,
                                                        uint32_t* __restrict__ out) {
    int i = blockIdx.x * 256 + threadIdx.x;
    if (i >= (D_ / 2) * (D_ / 4)) return;
    int n4 = D_ >> 2;
    int kp_g = i / n4;
    int n0 = (i % n4) << 2;
    int kt = kp_g >> 4, kp = kp_g & 15;
    const int nkt = D_ >> 5;
    const float4* srcs[3] = {wq, wk, wv};
#pragma unroll
    for (int s = 0; s < 3; s++) {
        float4 lo = srcs[s][(size_t)(2 * kp_g) * n4 + (n0 >> 2)];
        float4 hi = srcs[s][(size_t)(2 * kp_g + 1) * n4 + (n0 >> 2)];
        int n_glob = s * 1024 + n0;
        int bx = n_glob >> 8;
        uint32_t* blk = out + ((size_t)bx * nkt + kt) * 4096;
        float flo[4] = {lo.x, lo.y, lo.z, lo.w};
        float fhi[4] = {hi.x, hi.y, hi.z, hi.w};
#pragma unroll
        for (int j = 0; j < 4; j++)
            blk[wperm_addr(kp, (n_glob & 255) + j)] = pack_h2(flo[j], fhi[j]);
    }
}

__global__ __launch_bounds__(256) void pack_bqkv_kernel(const float* __restrict__ bq,
                                                        const float* __restrict__ bk,
                                                        const float* __restrict__ bv,
                                                        float* __restrict__ o) {
    int i = blockIdx.x * 256 + threadIdx.x;
    if (i >= L_ * 3 * D_) return;
    int l = i / (3 * D_), j = i % (3 * D_);
    float v;
    if (j < D_)           v = bq[l * D_ + j];
    else if (j < 2 * D_)  v = bk[l * D_ + j - D_];
    else                  v = bv[l * D_ + j - 2 * D_];
    o[i] = v;
}

// x -> g (fp32) + h_g (fp16)
__global__ __launch_bounds__(256) void copyx_kernel(const float4* __restrict__ in,
                                                    float4* __restrict__ out,
                                                    uint32_t* __restrict__ out16, int n4) {
    int i = blockIdx.x * 256 + threadIdx.x;
    if (i < n4) {
        float4 v = in[i];
        out[i] = v;
        uint2 u = make_uint2(pack_h2(v.x, v.y), pack_h2(v.z, v.w));
        *(uint2*)(out16 + i * 2) = u;
    }
}

// ---------------------------------------------------------------------------
// FP16 tensor-core GEMM (m16n8k16), cp.async 4-stage pipeline, permuted B.
// (unchanged from R15 — passing at 1419us)
// ---------------------------------------------------------------------------
#define BM 128
#define BN 256
#define BK 32
#define STAGES 4
#define A_STRIDE 20
#define A_WORDS (BM * A_STRIDE)
#define B_WORDS 4096
#define STAGE_WORDS (A_WORDS + B_WORDS)
#define GEMM_SMEM_BYTES (STAGES * STAGE_WORDS * 4)

__device__ __forceinline__ void mma_f16(float* c, uint32_t a0, uint32_t a1,
                                        uint32_t a2, uint32_t a3,
                                        uint32_t b0, uint32_t b1) {
    asm volatile(
        "mma.sync.aligned.m16n8k16.row.col.f32.f16.f16.f32 "
        "{%0,%1,%2,%3}, {%4,%5,%6,%7}, {%8,%9}, {%0,%1,%2,%3};"
        : "+f"(c[0]), "+f"(c[1]), "+f"(c[2]), "+f"(c[3])
        : "r"(a0), "r"(a1), "r"(a2), "r"(a3), "r"(b0), "r"(b1));
}

// OM: 0 = fp32 only, 2 = fp16 shadow only
template <bool RELU, int OM>
__global__ __launch_bounds__(256, 1) void tc_gemm_kernel(
        const __half* __restrict__ A, const uint32_t* __restrict__ W,
        const float* __restrict__ bias, float* __restrict__ C,
        void* __restrict__ CS, int M, int N, int K) {
    extern __shared__ __align__(16) uint32_t sm[];
    uint32_t smb = (uint32_t)__cvta_generic_to_shared(sm);

    int tid = threadIdx.x;
    int bx = blockIdx.x, by = blockIdx.y;
    int wid = tid >> 5, lane = tid & 31;
    int warp_m = wid >> 2;
    int warp_n = wid & 3;
    int g = lane >> 2, t4 = lane & 3;

    const __half* Ag = A + (size_t)by * BM * K;
    const uint32_t* Wg = W + (size_t)bx * (K >> 5) * 4096;

    auto issue = [&](int s, int kt) {
        uint32_t base = smb + (uint32_t)(s * STAGE_WORDS) * 4u;
#pragma unroll
        for (int r = 0; r < 2; r++) {
            int c = tid + r * 256;
            int row = c >> 2, u = c & 3;
            cp16(base + (uint32_t)(row * A_STRIDE + u * 4) * 4u,
                 Ag + (size_t)row * K + kt + u * 8);
        }
        uint32_t baseB = base + (uint32_t)A_WORDS * 4u;
        const uint32_t* Wsrc = Wg + (size_t)(kt >> 5) * 4096;
#pragma unroll
        for (int r = 0; r < 4; r++) {
            int c = tid + r * 256;
            cp16(baseB + (uint32_t)c * 16u, Wsrc + c * 4);
        }
        asm volatile("cp.async.commit_group;\n" ::);
    };

    float acc[4][8][4];
#pragma unroll
    for (int mi = 0; mi < 4; mi++)
#pragma unroll
        for (int nj = 0; nj < 8; nj++)
#pragma unroll
            for (int e = 0; e < 4; e++) acc[mi][nj][e] = 0.f;

    int nk = K / BK;
    issue(0, 0);
    issue(1, BK);
    issue(2, 2 * BK);
    asm volatile("cp.async.wait_group %0;\n" :: "n"(2));
    __syncthreads();

    for (int t = 0; t < nk; t++) {
        int pf = t + STAGES - 1;
        if (pf < nk) issue(pf % STAGES, pf * BK);

        const uint32_t* As = sm + (t % STAGES) * STAGE_WORDS;
        const uint32_t* Bs = As + A_WORDS;

        uint32_t af[2][4][4];
        uint4 bq[2][4];
#pragma unroll
        for (int s = 0; s < 2; s++) {
            int acol = s * 8 + t4;
#pragma unroll
            for (int mi = 0; mi < 4; mi++) {
                int r = warp_m * 64 + mi * 16 + g;
                af[s][mi][0] = As[r * A_STRIDE + acol];
                af[s][mi][1] = As[(r + 8) * A_STRIDE + acol];
                af[s][mi][2] = As[r * A_STRIDE + acol + 4];
                af[s][mi][3] = As[(r + 8) * A_STRIDE + acol + 4];
            }
#pragma unroll
            for (int nq = 0; nq < 4; nq++)
                bq[s][nq] = *(const uint4*)&Bs[(((s * 16) + warp_n * 4 + nq) * 32
                                               + g * 4 + t4) * 4];
        }
#pragma unroll
        for (int s = 0; s < 2; s++)
#pragma unroll
            for (int mi = 0; mi < 4; mi++)
#pragma unroll
                for (int nq = 0; nq < 4; nq++) {
                    mma_f16(acc[mi][2 * nq],     af[s][mi][0], af[s][mi][1],
                            af[s][mi][2], af[s][mi][3], bq[s][nq].x, bq[s][nq].y);
                    mma_f16(acc[mi][2 * nq + 1], af[s][mi][0], af[s][mi][1],
                            af[s][mi][2], af[s][mi][3], bq[s][nq].z, bq[s][nq].w);
                }

        if (t + 4 <= nk)
            asm volatile("cp.async.wait_group %0;\n" :: "n"(2));
        else if (t + 3 == nk)
            asm volatile("cp.async.wait_group %0;\n" :: "n"(1));
        else
            asm volatile("cp.async.wait_group %0;\n" :: "n"(0));
        __syncthreads();
    }

    int row0 = by * BM + warp_m * 64;
    int col0 = bx * BN + warp_n * 64;
#pragma unroll
    for (int nj = 0; nj < 8; nj++) {
        int cc = col0 + nj * 8 + t4 * 2;
        float b0 = bias[cc], b1 = bias[cc + 1];
#pragma unroll
        for (int mi = 0; mi < 4; mi++) {
            int r = row0 + mi * 16 + g;
            float v00 = acc[mi][nj][0] + b0, v01 = acc[mi][nj][1] + b1;
            float v10 = acc[mi][nj][2] + b0, v11 = acc[mi][nj][3] + b1;
            if (RELU) {
                v00 = fmaxf(v00, 0.f); v01 = fmaxf(v01, 0.f);
                v10 = fmaxf(v10, 0.f); v11 = fmaxf(v11, 0.f);
            }
            if (OM == 0) {
                *(float2*)(C + (size_t)r * N + cc) = make_float2(v00, v01);
                *(float2*)(C + (size_t)(r + 8) * N + cc) = make_float2(v10, v11);
            }
            if (OM == 2) {
                __half* CH = (__half*)CS;
                *(uint32_t*)(CH + (size_t)r * N + cc) = pack_h2(v00, v01);
                *(uint32_t*)(CH + (size_t)(r + 8) * N + cc) = pack_h2(v10, v11);
            }
        }
    }
}

// ---------------------------------------------------------------------------
// FP16 flash attention, cp.async KV pipeline, 2 syncs per iteration.
// Buffers: Q [64][36], K [64][36], V0/V1 [64][36], Ps fp32 [64][66], Pu [64][36].
// ---------------------------------------------------------------------------
#define A2_Q   0
#define A2_K   2304
#define A2_V0  4608
#define A2_V1  6912
#define A2_PS  9216
#define A2_PU  13440
#define A2_AUX 15744
#define A2_WORDS (15744 + 192)
#define A2_BYTES (A2_WORDS * 4)

__global__ __launch_bounds__(256) void attn_f16_kernel(const uint32_t* __restrict__ QKVw,
                                                       __half* __restrict__ O16) {
    extern __shared__ __align__(16) uint32_t smu[];
    uint32_t smb = (uint32_t)__cvta_generic_to_shared(smu);
    uint32_t* Qs = smu + A2_Q;
    uint32_t* Ks = smu + A2_K;
    float*    Ps = (float*)(smu + A2_PS);
    uint32_t* Pu = smu + A2_PU;
    float*    m_s = (float*)(smu + A2_AUX);
    float*    l_s = m_s + 64;
    float*    a_s = l_s + 64;

    int tid = threadIdx.x;
    int b = blockIdx.x >> 4, h = blockIdx.x & 15;
    int q0 = blockIdx.y * 64;
    int wid = tid >> 5, lane = tid & 31;
    int m0 = (wid >> 1) * 16;
    int n0 = (wid & 1) * 32;
    int g = lane >> 2, t4 = lane & 3;

    // prologue: Q, K(0), V(0) via cp.async
    size_t base_q = (size_t)(b * S_ + q0) * 1536 + h * 32;
    size_t base_kv0 = (size_t)(b * S_) * 1536 + h * 32;
#pragma unroll
    for (int r = 0; r < 2; r++) {
        int idx = tid + r * 256;
        int row = idx >> 3, c = (idx & 7) * 4;
        cp16(smb + (uint32_t)(A2_Q + row * 36 + c) * 4u,
             QKVw + base_q + (size_t)row * 1536 + c);
        cp16(smb + (uint32_t)(A2_K + row * 36 + c) * 4u,
             QKVw + base_kv0 + 512 + (size_t)row * 1536 + c);
        cp16(smb + (uint32_t)(A2_V0 + row * 36 + c) * 4u,
             QKVw + base_kv0 + 1024 + (size_t)row * 1536 + c);
    }
    asm volatile("cp.async.commit_group;\n" ::);
    if (tid < 64) { m_s[tid] = -1e30f; l_s[tid] = 0.f; }
    asm volatile("cp.async.wait_group 0;\n" ::);
    __syncthreads();

    float acc_o[4][4];
#pragma unroll
    for (int nj = 0; nj < 4; nj++)
#pragma unroll
        for (int e = 0; e < 4; e++) acc_o[nj][e] = 0.f;

    for (int kt = 0; kt < 16; kt++) {
        // S = Q K^T from Qs, Ks
        float acc_s[4][4];
#pragma unroll
        for (int nj = 0; nj < 4; nj++)
#pragma unroll
            for (int e = 0; e < 4; e++) acc_s[nj][e] = 0.f;
#pragma unroll
        for (int s = 0; s < 4; s++) {
            int kp = s * 8 + t4;
            uint32_t a0 = Qs[(m0 + g) * 36 + kp];
            uint32_t a1 = Qs[(m0 + 8 + g) * 36 + kp];
            uint32_t a2 = Qs[(m0 + g) * 36 + kp + 4];
            uint32_t a3 = Qs[(m0 + 8 + g) * 36 + kp + 4];
#pragma unroll
            for (int nj = 0; nj < 4; nj++) {
                int key = n0 + nj * 8 + g;
                uint32_t b0 = Ks[key * 36 + kp];
                uint32_t b1 = Ks[key * 36 + kp + 4];
                mma_f16(acc_s[nj], a0, a1, a2, a3, b0, b1);
            }
        }
#pragma unroll
        for (int nj = 0; nj < 4; nj++) {
            int cc = n0 + nj * 8 + t4 * 2;
            *(float2*)&Ps[(m0 + g) * 66 + cc] =
                make_float2(acc_s[nj][0] * 0.125f, acc_s[nj][1] * 0.125f);
            *(float2*)&Ps[(m0 + 8 + g) * 66 + cc] =
                make_float2(acc_s[nj][2] * 0.125f, acc_s[nj][3] * 0.125f);
        }
        __syncthreads();   // sync1: S done (Ks free, Ps ready, prev PV done)

        // issue next K/V async (overlaps softmax)
        if (kt + 1 < 16) {
            size_t base_kv = (size_t)(b * S_ + (kt + 1) * 64) * 1536 + h * 32;
            uint32_t voff = ((kt + 1) & 1) ? A2_V1 : A2_V0;
#pragma unroll
            for (int r = 0; r < 2; r++) {
                int idx = tid + r * 256;
                int row = idx >> 3, c = (idx & 7) * 4;
                cp16(smb + (uint32_t)(A2_K + row * 36 + c) * 4u,
                     QKVw + base_kv + 512 + (size_t)row * 1536 + c);
                cp16(smb + (uint32_t)(voff + row * 36 + c) * 4u,
                     QKVw + base_kv + 1024 + (size_t)row * 1536 + c);
            }
            asm volatile("cp.async.commit_group;\n" ::);
        }

        // softmax Ps -> Pu (fp16 pairs), 4 lanes per row
        {
            int r = tid >> 2;
            int qd = tid & 3;
            float* Pr = Ps + r * 66 + qd * 16;
            uint32_t* Pru = Pu + r * 36 + qd * 8;
            float mx = -1e30f;
#pragma unroll
            for (int j = 0; j < 16; j++) mx = fmaxf(mx, Pr[j]);
            mx = fmaxf(mx, __shfl_xor_sync(0xffffffffu, mx, 1));
            mx = fmaxf(mx, __shfl_xor_sync(0xffffffffu, mx, 2));
            float mold = m_s[r];
            mx = fmaxf(mx, mold);
            float sum = 0.f;
#pragma unroll
            for (int j = 0; j < 8; j++) {
                float e0 = __expf(Pr[2 * j] - mx);
                float e1 = __expf(Pr[2 * j + 1] - mx);
                Pru[j] = pack_h2(e0, e1);
                sum += e0;
                sum += e1;
            }
            sum += __shfl_xor_sync(0xffffffffu, sum, 1);
            sum += __shfl_xor_sync(0xffffffffu, sum, 2);
            if (qd == 0) {
                float al = __expf(mold - mx);
                l_s[r] = l_s[r] * al + sum;
                m_s[r] = mx;
                a_s[r] = al;
            }
        }
        if (kt + 1 < 16)
            asm volatile("cp.async.wait_group 0;\n" ::);
        __syncthreads();   // sync2: Pu ready, K(t+1)/V(t+1) landed

        // PV from V buffer (kt & 1)
        const uint32_t* Vs = smu + ((kt & 1) ? A2_V1 : A2_V0);
        float al0 = a_s[m0 + g], al1 = a_s[m0 + 8 + g];
#pragma unroll
        for (int nj = 0; nj < 4; nj++) {
            acc_o[nj][0] *= al0; acc_o[nj][1] *= al0;
            acc_o[nj][2] *= al1; acc_o[nj][3] *= al1;
        }
        uint32_t sel = (g & 1) ? 0x7632u : 0x5410u;
#pragma unroll
        for (int s = 0; s < 4; s++) {
            int kp = s * 8 + t4;
            uint32_t a0 = Pu[(m0 + g) * 36 + kp];
            uint32_t a1 = Pu[(m0 + 8 + g) * 36 + kp];
            uint32_t a2 = Pu[(m0 + g) * 36 + kp + 4];
            uint32_t a3 = Pu[(m0 + 8 + g) * 36 + kp + 4];
#pragma unroll
            for (int nj = 0; nj < 4; nj++) {
                int hdw = (n0 + nj * 8 + g) >> 1;
                uint32_t w0 = Vs[(2 * kp) * 36 + hdw];
                uint32_t w1 = Vs[(2 * kp + 1) * 36 + hdw];
                uint32_t x0 = Vs[(2 * kp + 8) * 36 + hdw];
                uint32_t x1 = Vs[(2 * kp + 9) * 36 + hdw];
                uint32_t b0 = __byte_perm(w0, w1, sel);
                uint32_t b1 = __byte_perm(x0, x1, sel);
                mma_f16(acc_o[nj], a0, a1, a2, a3, b0, b1);
            }
        }
        // no sync here: next S reads Qs/Ks only; Ps overwrite is pre-sync1-safe
    }

    float inv0 = 1.f / l_s[m0 + g];
    float inv1 = 1.f / l_s[m0 + 8 + g];
    size_t base_o = ((size_t)(b * S_ + q0)) * D_ + h * 64;
#pragma unroll
    for (int nj = 0; nj < 4; nj++) {
        int cc = n0 + nj * 8 + t4 * 2;
        *(uint32_t*)(O16 + base_o + (size_t)(m0 + g) * D_ + cc) =
            pack_h2(acc_o[nj][0] * inv0, acc_o[nj][1] * inv0);
        *(uint32_t*)(O16 + base_o + (size_t)(m0 + 8 + g) * D_ + cc) =
            pack_h2(acc_o[nj][2] * inv1, acc_o[nj][3] * inv1);
    }
}

// ---------------------------------------------------------------------------
// Fused residual + LayerNorm (optional fp16 shadow)
// ---------------------------------------------------------------------------
template <bool WH>
__global__ __launch_bounds__(256) void ln_kernel(const float* __restrict__ res,
                                                 const float* __restrict__ delta,
                                                 const float* __restrict__ gamma,
                                                 const float* __restrict__ beta,
                                                 float* __restrict__ out,
                                                 __half* __restrict__ out16) {
    int row = blockIdx.x, tid = threadIdx.x;
    size_t base = (size_t)row * D_;
    float4 rv = *(const float4*)(res + base + tid * 4);
    float4 dv = *(const float4*)(delta + base + tid * 4);
    float v0 = rv.x + dv.x, v1 = rv.y + dv.y, v2 = rv.z + dv.z, v3 = rv.w + dv.w;
    float s = v0 + v1 + v2 + v3;
    float q = v0 * v0 + v1 * v1 + v2 * v2 + v3 * v3;
#pragma unroll
    for (int o2 = 16; o2 > 0; o2 >>= 1) {
        s += __shfl_xor_sync(0xffffffffu, s, o2);
        q += __shfl_xor_sync(0xffffffffu, q, o2);
    }
    __shared__ float ss[8], qs[8];
    __shared__ float mean_s, rstd_s;
    if ((tid & 31) == 0) { ss[tid >> 5] = s; qs[tid >> 5] = q; }
    __syncthreads();
    if (tid == 0) {
        float S2 = 0.f, Q2 = 0.f;
#pragma unroll
        for (int w = 0; w < 8; w++) { S2 += ss[w]; Q2 += qs[w]; }
        float mean = S2 * (1.0f / D_);
        float var = Q2 * (1.0f / D_) - mean * mean;
        mean_s = mean;
        rstd_s = rsqrtf(var + 1e-5f);
    }
    __syncthreads();
    float mean = mean_s, rstd = rstd_s;
    float4 gv = *(const float4*)(gamma + tid * 4);
    float4 bv = *(const float4*)(beta + tid * 4);
    float4 ov;
    ov.x = (v0 - mean) * rstd * gv.x + bv.x;
    ov.y = (v1 - mean) * rstd * gv.y + bv.y;
    ov.z = (v2 - mean) * rstd * gv.z + bv.z;
    ov.w = (v3 - mean) * rstd * gv.w + bv.w;
    *(float4*)(out + base + tid * 4) = ov;
    if (WH) {
        uint2 u = make_uint2(pack_h2(ov.x, ov.y), pack_h2(ov.z, ov.w));
        *(uint2*)(out16 + base + tid * 4) = u;
    }
}

// ---------------------------------------------------------------------------
// Fused combine + LN2: v = g + pad(local2) + pad(local4); w = v + x;
// out16 = fp16(v) [feeds final FFN]; hout = LN(w)*gamma+beta [feeds final LN path]
// ---------------------------------------------------------------------------
__global__ __launch_bounds__(256) void combine_ln2_kernel(const float* __restrict__ g,
                                                          const float* __restrict__ y24,
                                                          const float* __restrict__ x,
                                                          const float* __restrict__ gamma,
                                                          const float* __restrict__ beta,
                                                          float* __restrict__ hout,
                                                          __half* __restrict__ out16) {
    int row = blockIdx.x, tid = threadIdx.x;
    int bb = row >> 10;
    int sp = row & 1023;
    size_t i = (size_t)row * 256 + tid;    // float4 index
    float4 v = ((const float4*)g)[i];
    if (sp >= 512) {
        float4 a = ((const float4*)y24)[((size_t)(bb * 512 + (sp - 512)) << 8) + tid];
        v.x += a.x; v.y += a.y; v.z += a.z; v.w += a.w;
    }
    if (sp >= 768) {
        float4 a = ((const float4*)y24)[((size_t)(2048 + bb * 256 + (sp - 768)) << 8) + tid];
        v.x += a.x; v.y += a.y; v.z += a.z; v.w += a.w;
    }
    // fp16 shadow of v (os)
    uint2 u = make_uint2(pack_h2(v.x, v.y), pack_h2(v.z, v.w));
    *(uint2*)(out16 + i * 4) = u;
    // w = v + x; LN(w)
    float4 xv = ((const float4*)x)[i];
    float w0 = v.x + xv.x, w1 = v.y + xv.y, w2 = v.z + xv.z, w3 = v.w + xv.w;
    float s = w0 + w1 + w2 + w3;
    float q = w0 * w0 + w1 * w1 + w2 * w2 + w3 * w3;
#pragma unroll
    for (int o2 = 16; o2 > 0; o2 >>= 1) {
        s += __shfl_xor_sync(0xffffffffu, s, o2);
        q += __shfl_xor_sync(0xffffffffu, q, o2);
    }
    __shared__ float ss[8], qs[8];
    __shared__ float mean_s, rstd_s;
    if ((tid & 31) == 0) { ss[tid >> 5] = s; qs[tid >> 5] = q; }
    __syncthreads();
    if (tid == 0) {
        float S2 = 0.f, Q2 = 0.f;
#pragma unroll
        for (int w = 0; w < 8; w++) { S2 += ss[w]; Q2 += qs[w]; }
        float mean = S2 * (1.0f / D_);
        float var = Q2 * (1.0f / D_) - mean * mean;
        mean_s = mean;
        rstd_s = rsqrtf(var + 1e-5f);
    }
    __syncthreads();
    float mean = mean_s, rstd = rstd_s;
    float4 gv = *(const float4*)(gamma + tid * 4);
    float4 bv = *(const float4*)(beta + tid * 4);
    float4 ov;
    ov.x = (w0 - mean) * rstd * gv.x + bv.x;
    ov.y = (w1 - mean) * rstd * gv.y + bv.y;
    ov.z = (w2 - mean) * rstd * gv.z + bv.z;
    ov.w = (w3 - mean) * rstd * gv.w + bv.w;
    ((float4*)hout)[i] = ov;
}

// ---------------------------------------------------------------------------
__global__ __launch_bounds__(256) void gather_fused_kernel(const float* __restrict__ x,
                                                           float* __restrict__ xs,
                                                           __half* __restrict__ xs16) {
    int row = blockIdx.x;
    int c = threadIdx.x;
    int tok;
    if (row < 2048) {
        int b = row >> 9, sl = row & 511;
        tok = b * S_ + 512 + sl;
    } else {
        int r2 = row - 2048;
        int b = r2 >> 8, sl = r2 & 255;
        tok = b * S_ + 768 + sl;
    }
    float4 v = ((const float4*)x)[((size_t)tok << 8) + c];
    size_t di = ((size_t)row << 8) + c;
    ((float4*)xs)[di] = v;
    uint2 u = make_uint2(pack_h2(v.x, v.y), pack_h2(v.z, v.w));
    *(uint2*)(xs16 + di * 4) = u;
}

// ---------------------------------------------------------------------------
// Host orchestration
// ---------------------------------------------------------------------------
enum GemmOut { OUT_F32 = 0, OUT_F16 = 2 };

static void launch_gemm(const __half* A, const uint32_t* W, const float* bias,
                        float* C, void* CS, int M, int N, int K,
                        bool relu, GemmOut mode, cudaStream_t st) {
    dim3 grid(N / BN, M / BM);
    if (mode == OUT_F32) {
        tc_gemm_kernel<false, 0><<<grid, 256, GEMM_SMEM_BYTES, st>>>(A, W, bias, C, CS, M, N, K);
    } else if (relu) {
        tc_gemm_kernel<true, 2><<<grid, 256, GEMM_SMEM_BYTES, st>>>(A, W, bias, C, CS, M, N, K);
    } else {
        tc_gemm_kernel<false, 2><<<grid, 256, GEMM_SMEM_BYTES, st>>>(A, W, bias, C, CS, M, N, K);
    }
}

static void launch_cvtp(const float* src, uint32_t* dst, int K, int N, cudaStream_t st) {
    int nthr = (K / 2) * (N / 4);
    cvtwp_kernel<<<(nthr + 255) / 256, 256, 0, st>>>((const float4*)src, dst, K, N);
}

extern "C" void kernel_launch(void* const* d_in, const int* in_sizes, int n_in,
                              void* d_out, int out_size) {
    (void)in_sizes; (void)n_in; (void)out_size;
    const float* x    = (const float*)d_in[0];
    const float* Wq   = (const float*)d_in[1];
    const float* bq   = (const float*)d_in[2];
    const float* Wk   = (const float*)d_in[3];
    const float* bk   = (const float*)d_in[4];
    const float* Wv   = (const float*)d_in[5];
    const float* bv   = (const float*)d_in[6];
    const float* Wo   = (const float*)d_in[7];
    const float* bo   = (const float*)d_in[8];
    const float* W1   = (const float*)d_in[9];
    const float* b1   = (const float*)d_in[10];
    const float* W2   = (const float*)d_in[11];
    const float* b2   = (const float*)d_in[12];
    const float* n1s  = (const float*)d_in[13];
    const float* n1b  = (const float*)d_in[14];
    const float* n2s  = (const float*)d_in[15];
    const float* n2b  = (const float*)d_in[16];
    const float* ln1s = (const float*)d_in[17];
    const float* ln1b = (const float*)d_in[18];
    const float* ln2s = (const float*)d_in[19];
    const float* ln2b = (const float*)d_in[20];
    const float* ln3s = (const float*)d_in[21];
    const float* ln3b = (const float*)d_in[22];
    const float* Wb   = (const float*)d_in[23];
    const float* bb   = (const float*)d_in[24];
    const float* Wm   = (const float*)d_in[25];
    const float* bm   = (const float*)d_in[26];
    const float* Wf1  = (const float*)d_in[27];
    const float* bf1  = (const float*)d_in[28];
    const float* Wf2  = (const float*)d_in[29];
    const float* bf2  = (const float*)d_in[30];
    float* out = (float*)d_out;

    float *g, *q, *xs, *mo, *y24, *h, *bqkv;
    __half *hg, *hos, *hao, *hxs, *hmid, *hff, *hqkv;
    uint32_t *twqkv, *two, *tw1, *tw2, *twb, *twm, *twf1, *twf2;
    cudaGetSymbolAddress((void**)&g,  g_g);
    cudaGetSymbolAddress((void**)&q,  g_q);
    cudaGetSymbolAddress((void**)&xs, g_xs);
    cudaGetSymbolAddress((void**)&mo, g_mo);
    cudaGetSymbolAddress((void**)&y24, g_y24);
    cudaGetSymbolAddress((void**)&h,  g_h);
    cudaGetSymbolAddress((void**)&hg,  h_g);
    cudaGetSymbolAddress((void**)&hos, h_os);
    cudaGetSymbolAddress((void**)&hao, h_ao);
    cudaGetSymbolAddress((void**)&hxs, h_xs);
    cudaGetSymbolAddress((void**)&hmid, h_mid);
    cudaGetSymbolAddress((void**)&hff, h_ff);
    cudaGetSymbolAddress((void**)&hqkv, h_qkv);
    cudaGetSymbolAddress((void**)&twqkv, t_Wqkv);
    cudaGetSymbolAddress((void**)&bqkv, b_qkv);
    cudaGetSymbolAddress((void**)&two, t_Wo);
    cudaGetSymbolAddress((void**)&tw1, t_W1);
    cudaGetSymbolAddress((void**)&tw2, t_W2);
    cudaGetSymbolAddress((void**)&twb, t_Wb);
    cudaGetSymbolAddress((void**)&twm, t_Wm);
    cudaGetSymbolAddress((void**)&twf1, t_Wf1);
    cudaGetSymbolAddress((void**)&twf2, t_Wf2);

    cudaFuncSetAttribute(attn_f16_kernel, cudaFuncAttributeMaxDynamicSharedMemorySize, A2_BYTES);
    cudaFuncSetAttribute(tc_gemm_kernel<false, 0>,
                         cudaFuncAttributeMaxDynamicSharedMemorySize, GEMM_SMEM_BYTES);
    cudaFuncSetAttribute(tc_gemm_kernel<false, 2>,
                         cudaFuncAttributeMaxDynamicSharedMemorySize, GEMM_SMEM_BYTES);
    cudaFuncSetAttribute(tc_gemm_kernel<true, 2>,
                         cudaFuncAttributeMaxDynamicSharedMemorySize, GEMM_SMEM_BYTES);

    // ---- fork a side stream inside capture ----
    cudaStream_t side;
    cudaStreamCreateWithFlags(&side, cudaStreamNonBlocking);
    cudaEvent_t evFork, evCvt, evJoin;
    cudaEventCreateWithFlags(&evFork, cudaEventDisableTiming);
    cudaEventCreateWithFlags(&evCvt,  cudaEventDisableTiming);
    cudaEventCreateWithFlags(&evJoin, cudaEventDisableTiming);
    cudaEventRecord(evFork, 0);
    cudaStreamWaitEvent(side, evFork, 0);

    const int DD = D_ * D_;
    const int DF = D_ * F_;

    // ---- side stream: weight cvts (critical ones first), then locals chain ----
    launch_cvtp(Wo, two, D_, D_, side);
    launch_cvtp(Wo + DD, two + DD / 2, D_, D_, side);
    launch_cvtp(W1, tw1, D_, F_, side);
    launch_cvtp(W1 + DF, tw1 + DF / 2, D_, F_, side);
    launch_cvtp(W2, tw2, F_, D_, side);
    launch_cvtp(W2 + DF, tw2 + DF / 2, F_, D_, side);
    cvtwp_qkv_kernel<<<((D_ / 2) * (D_ / 4) + 255) / 256, 256, 0, side>>>(
        (const float4*)(Wq + DD), (const float4*)(Wk + DD), (const float4*)(Wv + DD),
        twqkv + (size_t)3 * DD / 2);
    cudaEventRecord(evCvt, side);
    launch_cvtp(Wf1, twf1, D_, F_, side);
    launch_cvtp(Wf2, twf2, F_, D_, side);
    launch_cvtp(Wb, twb, D_, M_, side);
    launch_cvtp(Wm, twm, M_, D_, side);
    gather_fused_kernel<<<RL_, 256, 0, side>>>(x, xs, hxs);
    launch_gemm(hxs, twb, bb, nullptr, hmid, RL_, M_, D_, false, OUT_F16, side);
    launch_gemm(hmid, twm, bm, mo, nullptr, RL_, D_, M_, false, OUT_F32, side);
    ln_kernel<false><<<RL_, 256, 0, side>>>(xs, mo, ln1s, ln1b, y24, nullptr);
    cudaEventRecord(evJoin, side);

    // ---- main stream ----
    cvtwp_qkv_kernel<<<((D_ / 2) * (D_ / 4) + 255) / 256, 256>>>(
        (const float4*)Wq, (const float4*)Wk, (const float4*)Wv, twqkv);
    pack_bqkv_kernel<<<(L_ * 3 * D_ + 255) / 256, 256>>>(bq, bk, bv, bqkv);
    copyx_kernel<<<N_ * D_ / 4 / 256, 256>>>((const float4*)x, (float4*)g,
                                             (uint32_t*)hg, N_ * D_ / 4);

    for (int i = 0; i < L_; i++) {
        launch_gemm(hg, twqkv + (size_t)i * 3 * DD / 2, bqkv + i * 3 * D_,
                    nullptr, hqkv, N_, 3 * D_, D_, false, OUT_F16, 0);
        attn_f16_kernel<<<dim3(B_ * H_, S_ / 64), 256, A2_BYTES>>>((const uint32_t*)hqkv, hao);
        if (i == 0) cudaStreamWaitEvent(0, evCvt, 0);
        launch_gemm(hao, two + (size_t)i * DD / 2, bo + i * D_, q, nullptr,
                    N_, D_, D_, false, OUT_F32, 0);
        ln_kernel<true><<<N_, 256>>>(g, q, n1s + i * D_, n1b + i * D_, g, hg);
        launch_gemm(hg, tw1 + (size_t)i * DF / 2, b1 + i * F_, nullptr, hff,
                    N_, F_, D_, true, OUT_F16, 0);
        launch_gemm(hff, tw2 + (size_t)i * DF / 2, b2 + i * D_, q, nullptr,
                    N_, D_, F_, false, OUT_F32, 0);
        ln_kernel<true><<<N_, 256>>>(g, q, n2s + i * D_, n2b + i * D_, g, hg);
    }

    cudaStreamWaitEvent(0, evJoin, 0);
    // fused: os16 = fp16(g + locals); h = LN(os + x)
    combine_ln2_kernel<<<N_, 256>>>(g, y24, x, ln2s, ln2b, h, hos);
    launch_gemm(hos, twf1, bf1, nullptr, hff, N_, F_, D_, true, OUT_F16, 0);
    launch_gemm(hff, twf2, bf2, q, nullptr, N_, D_, F_, false, OUT_F32, 0);
    ln_kernel<false><<<N_, 256>>>(h, q, ln3s, ln3b, out, nullptr);
}

// round 17
// speedup vs baseline: 1.0292x; 1.0292x over previous
#include <cuda_runtime.h>
#include <cuda_fp16.h>
#include <cstdint>
#include <cstddef>

// Problem constants
#define B_  4
#define S_  1024
#define D_  1024
#define F_  4096
#define M_  512
#define H_  16
#define HD_ 64
#define L_  2
#define N_  (B_ * S_)   // 4096 tokens
#define RL_ 3072        // fused local rows (2048 + 1024)

// ---------------------------------------------------------------------------
// Scratch buffers (static device globals; no runtime allocation)
// ---------------------------------------------------------------------------
__device__ float g_g [N_ * D_];
__device__ float g_q [N_ * D_];        // generic fp32 delta scratch
__device__ float g_xs [RL_ * D_];
__device__ float g_mo [RL_ * D_];
__device__ float g_y24[RL_ * D_];
__device__ float g_h [N_ * D_];
// fp16 shadow activations (GEMM A inputs)
__device__ __half h_g [N_ * D_];
__device__ __half h_os[N_ * D_];
__device__ __half h_ao[N_ * D_];
__device__ __half h_xs[RL_ * D_];
__device__ __half h_mid[RL_ * M_];
__device__ __half h_ff[N_ * F_];
__device__ __half h_qkv[N_ * 3 * D_];
// fp16 weight copies (PERMUTED half2 block layout)
__device__ uint32_t t_Wqkv[L_ * D_ * 3 * D_ / 2];
__device__ float    b_qkv [L_ * 3 * D_];
__device__ uint32_t t_Wo [L_ * D_ * D_ / 2];
__device__ uint32_t t_W1 [L_ * D_ * F_ / 2];
__device__ uint32_t t_W2 [L_ * F_ * D_ / 2];
__device__ uint32_t t_Wb [D_ * M_ / 2];
__device__ uint32_t t_Wm [M_ * D_ / 2];
__device__ uint32_t t_Wf1[D_ * F_ / 2];
__device__ uint32_t t_Wf2[F_ * D_ / 2];

// ---------------------------------------------------------------------------
__device__ __forceinline__ uint32_t pack_h2(float a, float b) {
    __half2 h = __floats2half2_rn(a, b);
    return *(uint32_t*)&h;
}

__device__ __forceinline__ void cp16(uint32_t dst_smem, const void* src) {
    asm volatile("cp.async.cg.shared.global [%0], [%1], 16;\n" :: "r"(dst_smem), "l"(src));
}

// Permuted block layout (uint = half2 pair of adjacent k).
__device__ __forceinline__ int wperm_addr(int kp, int nl) {
    int s = kp >> 3, t4 = kp & 3, hik = (kp >> 2) & 1;
    int ng = nl >> 4, cc = nl & 15, jj2 = cc >> 3, gg = cc & 7;
    return (((s * 16 + ng) * 32) + gg * 4 + t4) * 4 + hik + 2 * jj2;
}

// fp32 [K][N] -> permuted fp16 blocks.
__global__ __launch_bounds__(256) void cvtwp_kernel(const float4* __restrict__ in,
                                                    uint32_t* __restrict__ out,
                                                    int K, int N) {
    int i = blockIdx.x * 256 + threadIdx.x;
    int n4 = N >> 2;
    if (i >= (K >> 1) * n4) return;
    int kp_g = i / n4;
    int n0 = (i % n4) << 2;
    float4 lo = in[(size_t)(2 * kp_g) * n4 + (n0 >> 2)];
    float4 hi = in[(size_t)(2 * kp_g + 1) * n4 + (n0 >> 2)];
    int kt = kp_g >> 4, kp = kp_g & 15;
    int bx = n0 >> 8;
    int nkt = K >> 5;
    uint32_t* blk = out + ((size_t)bx * nkt + kt) * 4096;
    float flo[4] = {lo.x, lo.y, lo.z, lo.w};
    float fhi[4] = {hi.x, hi.y, hi.z, hi.w};
#pragma unroll
    for (int j = 0; j < 4; j++)
        blk[wperm_addr(kp, (n0 & 255) + j)] = pack_h2(flo[j], fhi[j]);
}

// Pack Wq|Wk|Wv (one layer) into [1024][3072] permuted fp16 blocks
__global__ __launch_bounds__(256) void cvtwp_qkv_kernel(const float4* __restrict__ wq,
                                                        const float4* __restrict__ wk,
                                                        const float4* __restrict__ wv,
                                                        uint32_t* __restrict__ out) {
    int i = blockIdx.x * 256 + threadIdx.x;
    if (i >= (D_ / 2) * (D_ / 4)) return;
    int n4 = D_ >> 2;
    int kp_g = i / n4;
    int n0 = (i % n4) << 2;
    int kt = kp_g >> 4, kp = kp_g & 15;
    const int nkt = D_ >> 5;
    const float4* srcs[3] = {wq, wk, wv};
#pragma unroll
    for (int s = 0; s < 3; s++) {
        float4 lo = srcs[s][(size_t)(2 * kp_g) * n4 + (n0 >> 2)];
        float4 hi = srcs[s][(size_t)(2 * kp_g + 1) * n4 + (n0 >> 2)];
        int n_glob = s * 1024 + n0;
        int bx = n_glob >> 8;
        uint32_t* blk = out + ((size_t)bx * nkt + kt) * 4096;
        float flo[4] = {lo.x, lo.y, lo.z, lo.w};
        float fhi[4] = {hi.x, hi.y, hi.z, hi.w};
#pragma unroll
        for (int j = 0; j < 4; j++)
            blk[wperm_addr(kp, (n_glob & 255) + j)] = pack_h2(flo[j], fhi[j]);
    }
}

__global__ __launch_bounds__(256) void pack_bqkv_kernel(const float* __restrict__ bq,
                                                        const float* __restrict__ bk,
                                                        const float* __restrict__ bv,
                                                        float* __restrict__ o) {
    int i = blockIdx.x * 256 + threadIdx.x;
    if (i >= L_ * 3 * D_) return;
    int l = i / (3 * D_), j = i % (3 * D_);
    float v;
    if (j < D_)           v = bq[l * D_ + j];
    else if (j < 2 * D_)  v = bk[l * D_ + j - D_];
    else                  v = bv[l * D_ + j - 2 * D_];
    o[i] = v;
}

// x -> g (fp32) + h_g (fp16)
__global__ __launch_bounds__(256) void copyx_kernel(const float4* __restrict__ in,
                                                    float4* __restrict__ out,
                                                    uint32_t* __restrict__ out16, int n4) {
    int i = blockIdx.x * 256 + threadIdx.x;
    if (i < n4) {
        float4 v = in[i];
        out[i] = v;
        uint2 u = make_uint2(pack_h2(v.x, v.y), pack_h2(v.z, v.w));
        *(uint2*)(out16 + i * 2) = u;
    }
}

// ---------------------------------------------------------------------------
// FP16 tensor-core GEMM (m16n8k16), cp.async 4-stage pipeline, permuted B,
// A fragments via ldmatrix.x4 (8 LDSM per warp per k-tile vs 32 LDS.32).
// ---------------------------------------------------------------------------
#define BM 128
#define BN 256
#define BK 32
#define STAGES 4
#define A_STRIDE 20
#define A_WORDS (BM * A_STRIDE)
#define B_WORDS 4096
#define STAGE_WORDS (A_WORDS + B_WORDS)
#define GEMM_SMEM_BYTES (STAGES * STAGE_WORDS * 4)

__device__ __forceinline__ void mma_f16(float* c, uint32_t a0, uint32_t a1,
                                        uint32_t a2, uint32_t a3,
                                        uint32_t b0, uint32_t b1) {
    asm volatile(
        "mma.sync.aligned.m16n8k16.row.col.f32.f16.f16.f32 "
        "{%0,%1,%2,%3}, {%4,%5,%6,%7}, {%8,%9}, {%0,%1,%2,%3};"
        : "+f"(c[0]), "+f"(c[1]), "+f"(c[2]), "+f"(c[3])
        : "r"(a0), "r"(a1), "r"(a2), "r"(a3), "r"(b0), "r"(b1));
}

__device__ __forceinline__ void ldsm4(uint32_t* r, uint32_t addr) {
    asm volatile("ldmatrix.sync.aligned.m8n8.x4.shared.b16 {%0,%1,%2,%3}, [%4];"
                 : "=r"(r[0]), "=r"(r[1]), "=r"(r[2]), "=r"(r[3]) : "r"(addr));
}

// OM: 0 = fp32 only, 2 = fp16 shadow only
template <bool RELU, int OM>
__global__ __launch_bounds__(256, 1) void tc_gemm_kernel(
        const __half* __restrict__ A, const uint32_t* __restrict__ W,
        const float* __restrict__ bias, float* __restrict__ C,
        void* __restrict__ CS, int M, int N, int K) {
    extern __shared__ __align__(16) uint32_t sm[];
    uint32_t smb = (uint32_t)__cvta_generic_to_shared(sm);

    int tid = threadIdx.x;
    int bx = blockIdx.x, by = blockIdx.y;
    int wid = tid >> 5, lane = tid & 31;
    int warp_m = wid >> 2;
    int warp_n = wid & 3;
    int g = lane >> 2, t4 = lane & 3;
    int lrow = lane & 15, lkh = lane >> 4;   // ldmatrix lane addressing

    const __half* Ag = A + (size_t)by * BM * K;
    const uint32_t* Wg = W + (size_t)bx * (K >> 5) * 4096;

    auto issue = [&](int s, int kt) {
        uint32_t base = smb + (uint32_t)(s * STAGE_WORDS) * 4u;
#pragma unroll
        for (int r = 0; r < 2; r++) {
            int c = tid + r * 256;
            int row = c >> 2, u = c & 3;
            cp16(base + (uint32_t)(row * A_STRIDE + u * 4) * 4u,
                 Ag + (size_t)row * K + kt + u * 8);
        }
        uint32_t baseB = base + (uint32_t)A_WORDS * 4u;
        const uint32_t* Wsrc = Wg + (size_t)(kt >> 5) * 4096;
#pragma unroll
        for (int r = 0; r < 4; r++) {
            int c = tid + r * 256;
            cp16(baseB + (uint32_t)c * 16u, Wsrc + c * 4);
        }
        asm volatile("cp.async.commit_group;\n" ::);
    };

    float acc[4][8][4];
#pragma unroll
    for (int mi = 0; mi < 4; mi++)
#pragma unroll
        for (int nj = 0; nj < 8; nj++)
#pragma unroll
            for (int e = 0; e < 4; e++) acc[mi][nj][e] = 0.f;

    int nk = K / BK;
    issue(0, 0);
    issue(1, BK);
    issue(2, 2 * BK);
    asm volatile("cp.async.wait_group %0;\n" :: "n"(2));
    __syncthreads();

    for (int t = 0; t < nk; t++) {
        int pf = t + STAGES - 1;
        if (pf < nk) issue(pf % STAGES, pf * BK);

        uint32_t sa = smb + (uint32_t)((t % STAGES) * STAGE_WORDS) * 4u;
        const uint32_t* Bs = sm + (t % STAGES) * STAGE_WORDS + A_WORDS;

        uint32_t af[2][4][4];
        uint4 bq[2][4];
#pragma unroll
        for (int s = 0; s < 2; s++) {
#pragma unroll
            for (int mi = 0; mi < 4; mi++) {
                int row = warp_m * 64 + mi * 16 + lrow;
                ldsm4(af[s][mi],
                      sa + (uint32_t)(row * A_STRIDE + s * 8 + lkh * 4) * 4u);
            }
#pragma unroll
            for (int nq = 0; nq < 4; nq++)
                bq[s][nq] = *(const uint4*)&Bs[(((s * 16) + warp_n * 4 + nq) * 32
                                               + g * 4 + t4) * 4];
        }
#pragma unroll
        for (int s = 0; s < 2; s++)
#pragma unroll
            for (int mi = 0; mi < 4; mi++)
#pragma unroll
                for (int nq = 0; nq < 4; nq++) {
                    mma_f16(acc[mi][2 * nq],     af[s][mi][0], af[s][mi][1],
                            af[s][mi][2], af[s][mi][3], bq[s][nq].x, bq[s][nq].y);
                    mma_f16(acc[mi][2 * nq + 1], af[s][mi][0], af[s][mi][1],
                            af[s][mi][2], af[s][mi][3], bq[s][nq].z, bq[s][nq].w);
                }

        if (t + 4 <= nk)
            asm volatile("cp.async.wait_group %0;\n" :: "n"(2));
        else if (t + 3 == nk)
            asm volatile("cp.async.wait_group %0;\n" :: "n"(1));
        else
            asm volatile("cp.async.wait_group %0;\n" :: "n"(0));
        __syncthreads();
    }

    int row0 = by * BM + warp_m * 64;
    int col0 = bx * BN + warp_n * 64;
#pragma unroll
    for (int nj = 0; nj < 8; nj++) {
        int cc = col0 + nj * 8 + t4 * 2;
        float b0 = bias[cc], b1 = bias[cc + 1];
#pragma unroll
        for (int mi = 0; mi < 4; mi++) {
            int r = row0 + mi * 16 + g;
            float v00 = acc[mi][nj][0] + b0, v01 = acc[mi][nj][1] + b1;
            float v10 = acc[mi][nj][2] + b0, v11 = acc[mi][nj][3] + b1;
            if (RELU) {
                v00 = fmaxf(v00, 0.f); v01 = fmaxf(v01, 0.f);
                v10 = fmaxf(v10, 0.f); v11 = fmaxf(v11, 0.f);
            }
            if (OM == 0) {
                *(float2*)(C + (size_t)r * N + cc) = make_float2(v00, v01);
                *(float2*)(C + (size_t)(r + 8) * N + cc) = make_float2(v10, v11);
            }
            if (OM == 2) {
                __half* CH = (__half*)CS;
                *(uint32_t*)(CH + (size_t)r * N + cc) = pack_h2(v00, v01);
                *(uint32_t*)(CH + (size_t)(r + 8) * N + cc) = pack_h2(v10, v11);
            }
        }
    }
}

// ---------------------------------------------------------------------------
// FP16 flash attention (R15 version — known good at 1419us).
// ---------------------------------------------------------------------------
#define AT_Q2   0
#define AT_KV2  2304
#define AT_PS2  4608
#define AT_PU2  8832
#define AT_AUX2 11136
#define AT_WORDS2 (11136 + 192)
#define AT_BYTES2 (AT_WORDS2 * 4)

__global__ __launch_bounds__(256) void attn_f16_kernel(const uint32_t* __restrict__ QKVw,
                                                       __half* __restrict__ O16) {
    extern __shared__ __align__(16) uint32_t smu[];
    uint32_t* Qs  = smu + AT_Q2;
    uint32_t* KVs = smu + AT_KV2;
    float*    Ps  = (float*)(smu + AT_PS2);
    uint32_t* Pu  = smu + AT_PU2;
    float*    m_s = (float*)(smu + AT_AUX2);
    float*    l_s = m_s + 64;
    float*    a_s = l_s + 64;

    int tid = threadIdx.x;
    int b = blockIdx.x >> 4, h = blockIdx.x & 15;
    int q0 = blockIdx.y * 64;
    int wid = tid >> 5, lane = tid & 31;
    int m0 = (wid >> 1) * 16;
    int n0 = (wid & 1) * 32;
    int g = lane >> 2, t4 = lane & 3;

    size_t base_q = (size_t)(b * S_ + q0) * 1536 + h * 32;
#pragma unroll
    for (int r = 0; r < 2; r++) {
        int idx = tid + r * 256;
        int row = idx >> 3, c = (idx & 7) * 4;
        *(uint4*)&Qs[row * 36 + c] = *(const uint4*)(QKVw + base_q + (size_t)row * 1536 + c);
    }
    if (tid < 64) { m_s[tid] = -1e30f; l_s[tid] = 0.f; }

    float acc_o[4][4];
#pragma unroll
    for (int nj = 0; nj < 4; nj++)
#pragma unroll
        for (int e = 0; e < 4; e++) acc_o[nj][e] = 0.f;

    for (int kt = 0; kt < 16; kt++) {
        size_t base_kv = (size_t)(b * S_ + kt * 64) * 1536 + h * 32;
#pragma unroll
        for (int r = 0; r < 2; r++) {
            int idx = tid + r * 256;
            int row = idx >> 3, c = (idx & 7) * 4;
            *(uint4*)&KVs[row * 36 + c] =
                *(const uint4*)(QKVw + base_kv + 512 + (size_t)row * 1536 + c);
        }
        __syncthreads();

        float acc_s[4][4];
#pragma unroll
        for (int nj = 0; nj < 4; nj++)
#pragma unroll
            for (int e = 0; e < 4; e++) acc_s[nj][e] = 0.f;
#pragma unroll
        for (int s = 0; s < 4; s++) {
            int kp = s * 8 + t4;
            uint32_t a0 = Qs[(m0 + g) * 36 + kp];
            uint32_t a1 = Qs[(m0 + 8 + g) * 36 + kp];
            uint32_t a2 = Qs[(m0 + g) * 36 + kp + 4];
            uint32_t a3 = Qs[(m0 + 8 + g) * 36 + kp + 4];
#pragma unroll
            for (int nj = 0; nj < 4; nj++) {
                int key = n0 + nj * 8 + g;
                uint32_t b0 = KVs[key * 36 + kp];
                uint32_t b1 = KVs[key * 36 + kp + 4];
                mma_f16(acc_s[nj], a0, a1, a2, a3, b0, b1);
            }
        }
#pragma unroll
        for (int nj = 0; nj < 4; nj++) {
            int cc = n0 + nj * 8 + t4 * 2;
            *(float2*)&Ps[(m0 + g) * 66 + cc] =
                make_float2(acc_s[nj][0] * 0.125f, acc_s[nj][1] * 0.125f);
            *(float2*)&Ps[(m0 + 8 + g) * 66 + cc] =
                make_float2(acc_s[nj][2] * 0.125f, acc_s[nj][3] * 0.125f);
        }
        __syncthreads();

#pragma unroll
        for (int r = 0; r < 2; r++) {
            int idx = tid + r * 256;
            int row = idx >> 3, c = (idx & 7) * 4;
            *(uint4*)&KVs[row * 36 + c] =
                *(const uint4*)(QKVw + base_kv + 1024 + (size_t)row * 1536 + c);
        }
        {
            int r = tid >> 2;
            int qd = tid & 3;
            float* Pr = Ps + r * 66 + qd * 16;
            uint32_t* Pru = Pu + r * 36 + qd * 8;
            float vals[16];
#pragma unroll
            for (int j = 0; j < 16; j++) vals[j] = Pr[j];
            float mx = -1e30f;
#pragma unroll
            for (int j = 0; j < 16; j++) mx = fmaxf(mx, vals[j]);
            mx = fmaxf(mx, __shfl_xor_sync(0xffffffffu, mx, 1));
            mx = fmaxf(mx, __shfl_xor_sync(0xffffffffu, mx, 2));
            float mold = m_s[r];
            mx = fmaxf(mx, mold);
            float sum = 0.f;
            float ev[16];
#pragma unroll
            for (int j = 0; j < 16; j++) {
                ev[j] = __expf(vals[j] - mx);
                sum += ev[j];
            }
#pragma unroll
            for (int j = 0; j < 8; j++)
                Pru[j] = pack_h2(ev[2 * j], ev[2 * j + 1]);
            sum += __shfl_xor_sync(0xffffffffu, sum, 1);
            sum += __shfl_xor_sync(0xffffffffu, sum, 2);
            if (qd == 0) {
                float al = __expf(mold - mx);
                l_s[r] = l_s[r] * al + sum;
                m_s[r] = mx;
                a_s[r] = al;
            }
        }
        __syncthreads();

        float al0 = a_s[m0 + g], al1 = a_s[m0 + 8 + g];
#pragma unroll
        for (int nj = 0; nj < 4; nj++) {
            acc_o[nj][0] *= al0; acc_o[nj][1] *= al0;
            acc_o[nj][2] *= al1; acc_o[nj][3] *= al1;
        }
        uint32_t sel = (g & 1) ? 0x7632u : 0x5410u;
#pragma unroll
        for (int s = 0; s < 4; s++) {
            int kp = s * 8 + t4;
            uint32_t a0 = Pu[(m0 + g) * 36 + kp];
            uint32_t a1 = Pu[(m0 + 8 + g) * 36 + kp];
            uint32_t a2 = Pu[(m0 + g) * 36 + kp + 4];
            uint32_t a3 = Pu[(m0 + 8 + g) * 36 + kp + 4];
#pragma unroll
            for (int nj = 0; nj < 4; nj++) {
                int hdw = (n0 + nj * 8 + g) >> 1;
                uint32_t w0 = KVs[(2 * kp) * 36 + hdw];
                uint32_t w1 = KVs[(2 * kp + 1) * 36 + hdw];
                uint32_t x0 = KVs[(2 * kp + 8) * 36 + hdw];
                uint32_t x1 = KVs[(2 * kp + 9) * 36 + hdw];
                uint32_t b0 = __byte_perm(w0, w1, sel);
                uint32_t b1 = __byte_perm(x0, x1, sel);
                mma_f16(acc_o[nj], a0, a1, a2, a3, b0, b1);
            }
        }
        __syncthreads();
    }

    float inv0 = 1.f / l_s[m0 + g];
    float inv1 = 1.f / l_s[m0 + 8 + g];
    size_t base_o = ((size_t)(b * S_ + q0)) * D_ + h * 64;
#pragma unroll
    for (int nj = 0; nj < 4; nj++) {
        int cc = n0 + nj * 8 + t4 * 2;
        *(uint32_t*)(O16 + base_o + (size_t)(m0 + g) * D_ + cc) =
            pack_h2(acc_o[nj][0] * inv0, acc_o[nj][1] * inv0);
        *(uint32_t*)(O16 + base_o + (size_t)(m0 + 8 + g) * D_ + cc) =
            pack_h2(acc_o[nj][2] * inv1, acc_o[nj][3] * inv1);
    }
}

// ---------------------------------------------------------------------------
// Fused residual + LayerNorm (optional fp16 shadow)
// ---------------------------------------------------------------------------
template <bool WH>
__global__ __launch_bounds__(256) void ln_kernel(const float* __restrict__ res,
                                                 const float* __restrict__ delta,
                                                 const float* __restrict__ gamma,
                                                 const float* __restrict__ beta,
                                                 float* __restrict__ out,
                                                 __half* __restrict__ out16) {
    int row = blockIdx.x, tid = threadIdx.x;
    size_t base = (size_t)row * D_;
    float4 rv = *(const float4*)(res + base + tid * 4);
    float4 dv = *(const float4*)(delta + base + tid * 4);
    float v0 = rv.x + dv.x, v1 = rv.y + dv.y, v2 = rv.z + dv.z, v3 = rv.w + dv.w;
    float s = v0 + v1 + v2 + v3;
    float q = v0 * v0 + v1 * v1 + v2 * v2 + v3 * v3;
#pragma unroll
    for (int o2 = 16; o2 > 0; o2 >>= 1) {
        s += __shfl_xor_sync(0xffffffffu, s, o2);
        q += __shfl_xor_sync(0xffffffffu, q, o2);
    }
    __shared__ float ss[8], qs[8];
    __shared__ float mean_s, rstd_s;
    if ((tid & 31) == 0) { ss[tid >> 5] = s; qs[tid >> 5] = q; }
    __syncthreads();
    if (tid == 0) {
        float S2 = 0.f, Q2 = 0.f;
#pragma unroll
        for (int w = 0; w < 8; w++) { S2 += ss[w]; Q2 += qs[w]; }
        float mean = S2 * (1.0f / D_);
        float var = Q2 * (1.0f / D_) - mean * mean;
        mean_s = mean;
        rstd_s = rsqrtf(var + 1e-5f);
    }
    __syncthreads();
    float mean = mean_s, rstd = rstd_s;
    float4 gv = *(const float4*)(gamma + tid * 4);
    float4 bv = *(const float4*)(beta + tid * 4);
    float4 ov;
    ov.x = (v0 - mean) * rstd * gv.x + bv.x;
    ov.y = (v1 - mean) * rstd * gv.y + bv.y;
    ov.z = (v2 - mean) * rstd * gv.z + bv.z;
    ov.w = (v3 - mean) * rstd * gv.w + bv.w;
    *(float4*)(out + base + tid * 4) = ov;
    if (WH) {
        uint2 u = make_uint2(pack_h2(ov.x, ov.y), pack_h2(ov.z, ov.w));
        *(uint2*)(out16 + base + tid * 4) = u;
    }
}

// ---------------------------------------------------------------------------
// Fused combine + LN2: v = g + pad(local2) + pad(local4); w = v + x;
// out16 = fp16(v); hout = LN(w)*gamma+beta
// ---------------------------------------------------------------------------
__global__ __launch_bounds__(256) void combine_ln2_kernel(const float* __restrict__ g,
                                                          const float* __restrict__ y24,
                                                          const float* __restrict__ x,
                                                          const float* __restrict__ gamma,
                                                          const float* __restrict__ beta,
                                                          float* __restrict__ hout,
                                                          __half* __restrict__ out16) {
    int row = blockIdx.x, tid = threadIdx.x;
    int bb = row >> 10;
    int sp = row & 1023;
    size_t i = (size_t)row * 256 + tid;
    float4 v = ((const float4*)g)[i];
    if (sp >= 512) {
        float4 a = ((const float4*)y24)[((size_t)(bb * 512 + (sp - 512)) << 8) + tid];
        v.x += a.x; v.y += a.y; v.z += a.z; v.w += a.w;
    }
    if (sp >= 768) {
        float4 a = ((const float4*)y24)[((size_t)(2048 + bb * 256 + (sp - 768)) << 8) + tid];
        v.x += a.x; v.y += a.y; v.z += a.z; v.w += a.w;
    }
    uint2 u = make_uint2(pack_h2(v.x, v.y), pack_h2(v.z, v.w));
    *(uint2*)(out16 + i * 4) = u;
    float4 xv = ((const float4*)x)[i];
    float w0 = v.x + xv.x, w1 = v.y + xv.y, w2 = v.z + xv.z, w3 = v.w + xv.w;
    float s = w0 + w1 + w2 + w3;
    float q = w0 * w0 + w1 * w1 + w2 * w2 + w3 * w3;
#pragma unroll
    for (int o2 = 16; o2 > 0; o2 >>= 1) {
        s += __shfl_xor_sync(0xffffffffu, s, o2);
        q += __shfl_xor_sync(0xffffffffu, q, o2);
    }
    __shared__ float ss[8], qs[8];
    __shared__ float mean_s, rstd_s;
    if ((tid & 31) == 0) { ss[tid >> 5] = s; qs[tid >> 5] = q; }
    __syncthreads();
    if (tid == 0) {
        float S2 = 0.f, Q2 = 0.f;
#pragma unroll
        for (int w = 0; w < 8; w++) { S2 += ss[w]; Q2 += qs[w]; }
        float mean = S2 * (1.0f / D_);
        float var = Q2 * (1.0f / D_) - mean * mean;
        mean_s = mean;
        rstd_s = rsqrtf(var + 1e-5f);
    }
    __syncthreads();
    float mean = mean_s, rstd = rstd_s;
    float4 gv = *(const float4*)(gamma + tid * 4);
    float4 bv = *(const float4*)(beta + tid * 4);
    float4 ov;
    ov.x = (w0 - mean) * rstd * gv.x + bv.x;
    ov.y = (w1 - mean) * rstd * gv.y + bv.y;
    ov.z = (w2 - mean) * rstd * gv.z + bv.z;
    ov.w = (w3 - mean) * rstd * gv.w + bv.w;
    ((float4*)hout)[i] = ov;
}

// ---------------------------------------------------------------------------
__global__ __launch_bounds__(256) void gather_fused_kernel(const float* __restrict__ x,
                                                           float* __restrict__ xs,
                                                           __half* __restrict__ xs16) {
    int row = blockIdx.x;
    int c = threadIdx.x;
    int tok;
    if (row < 2048) {
        int b = row >> 9, sl = row & 511;
        tok = b * S_ + 512 + sl;
    } else {
        int r2 = row - 2048;
        int b = r2 >> 8, sl = r2 & 255;
        tok = b * S_ + 768 + sl;
    }
    float4 v = ((const float4*)x)[((size_t)tok << 8) + c];
    size_t di = ((size_t)row << 8) + c;
    ((float4*)xs)[di] = v;
    uint2 u = make_uint2(pack_h2(v.x, v.y), pack_h2(v.z, v.w));
    *(uint2*)(xs16 + di * 4) = u;
}

// ---------------------------------------------------------------------------
// Host orchestration
// ---------------------------------------------------------------------------
enum GemmOut { OUT_F32 = 0, OUT_F16 = 2 };

static void launch_gemm(const __half* A, const uint32_t* W, const float* bias,
                        float* C, void* CS, int M, int N, int K,
                        bool relu, GemmOut mode, cudaStream_t st) {
    dim3 grid(N / BN, M / BM);
    if (mode == OUT_F32) {
        tc_gemm_kernel<false, 0><<<grid, 256, GEMM_SMEM_BYTES, st>>>(A, W, bias, C, CS, M, N, K);
    } else if (relu) {
        tc_gemm_kernel<true, 2><<<grid, 256, GEMM_SMEM_BYTES, st>>>(A, W, bias, C, CS, M, N, K);
    } else {
        tc_gemm_kernel<false, 2><<<grid, 256, GEMM_SMEM_BYTES, st>>>(A, W, bias, C, CS, M, N, K);
    }
}

static void launch_cvtp(const float* src, uint32_t* dst, int K, int N, cudaStream_t st) {
    int nthr = (K / 2) * (N / 4);
    cvtwp_kernel<<<(nthr + 255) / 256, 256, 0, st>>>((const float4*)src, dst, K, N);
}

extern "C" void kernel_launch(void* const* d_in, const int* in_sizes, int n_in,
                              void* d_out, int out_size) {
    (void)in_sizes; (void)n_in; (void)out_size;
    const float* x    = (const float*)d_in[0];
    const float* Wq   = (const float*)d_in[1];
    const float* bq   = (const float*)d_in[2];
    const float* Wk   = (const float*)d_in[3];
    const float* bk   = (const float*)d_in[4];
    const float* Wv   = (const float*)d_in[5];
    const float* bv   = (const float*)d_in[6];
    const float* Wo   = (const float*)d_in[7];
    const float* bo   = (const float*)d_in[8];
    const float* W1   = (const float*)d_in[9];
    const float* b1   = (const float*)d_in[10];
    const float* W2   = (const float*)d_in[11];
    const float* b2   = (const float*)d_in[12];
    const float* n1s  = (const float*)d_in[13];
    const float* n1b  = (const float*)d_in[14];
    const float* n2s  = (const float*)d_in[15];
    const float* n2b  = (const float*)d_in[16];
    const float* ln1s = (const float*)d_in[17];
    const float* ln1b = (const float*)d_in[18];
    const float* ln2s = (const float*)d_in[19];
    const float* ln2b = (const float*)d_in[20];
    const float* ln3s = (const float*)d_in[21];
    const float* ln3b = (const float*)d_in[22];
    const float* Wb   = (const float*)d_in[23];
    const float* bb   = (const float*)d_in[24];
    const float* Wm   = (const float*)d_in[25];
    const float* bm   = (const float*)d_in[26];
    const float* Wf1  = (const float*)d_in[27];
    const float* bf1  = (const float*)d_in[28];
    const float* Wf2  = (const float*)d_in[29];
    const float* bf2  = (const float*)d_in[30];
    float* out = (float*)d_out;

    float *g, *q, *xs, *mo, *y24, *h, *bqkv;
    __half *hg, *hos, *hao, *hxs, *hmid, *hff, *hqkv;
    uint32_t *twqkv, *two, *tw1, *tw2, *twb, *twm, *twf1, *twf2;
    cudaGetSymbolAddress((void**)&g,  g_g);
    cudaGetSymbolAddress((void**)&q,  g_q);
    cudaGetSymbolAddress((void**)&xs, g_xs);
    cudaGetSymbolAddress((void**)&mo, g_mo);
    cudaGetSymbolAddress((void**)&y24, g_y24);
    cudaGetSymbolAddress((void**)&h,  g_h);
    cudaGetSymbolAddress((void**)&hg,  h_g);
    cudaGetSymbolAddress((void**)&hos, h_os);
    cudaGetSymbolAddress((void**)&hao, h_ao);
    cudaGetSymbolAddress((void**)&hxs, h_xs);
    cudaGetSymbolAddress((void**)&hmid, h_mid);
    cudaGetSymbolAddress((void**)&hff, h_ff);
    cudaGetSymbolAddress((void**)&hqkv, h_qkv);
    cudaGetSymbolAddress((void**)&twqkv, t_Wqkv);
    cudaGetSymbolAddress((void**)&bqkv, b_qkv);
    cudaGetSymbolAddress((void**)&two, t_Wo);
    cudaGetSymbolAddress((void**)&tw1, t_W1);
    cudaGetSymbolAddress((void**)&tw2, t_W2);
    cudaGetSymbolAddress((void**)&twb, t_Wb);
    cudaGetSymbolAddress((void**)&twm, t_Wm);
    cudaGetSymbolAddress((void**)&twf1, t_Wf1);
    cudaGetSymbolAddress((void**)&twf2, t_Wf2);

    cudaFuncSetAttribute(attn_f16_kernel, cudaFuncAttributeMaxDynamicSharedMemorySize, AT_BYTES2);
    cudaFuncSetAttribute(tc_gemm_kernel<false, 0>,
                         cudaFuncAttributeMaxDynamicSharedMemorySize, GEMM_SMEM_BYTES);
    cudaFuncSetAttribute(tc_gemm_kernel<false, 2>,
                         cudaFuncAttributeMaxDynamicSharedMemorySize, GEMM_SMEM_BYTES);
    cudaFuncSetAttribute(tc_gemm_kernel<true, 2>,
                         cudaFuncAttributeMaxDynamicSharedMemorySize, GEMM_SMEM_BYTES);

    // ---- fork a side stream inside capture ----
    cudaStream_t side;
    cudaStreamCreateWithFlags(&side, cudaStreamNonBlocking);
    cudaEvent_t evFork, evCvt, evJoin;
    cudaEventCreateWithFlags(&evFork, cudaEventDisableTiming);
    cudaEventCreateWithFlags(&evCvt,  cudaEventDisableTiming);
    cudaEventCreateWithFlags(&evJoin, cudaEventDisableTiming);
    cudaEventRecord(evFork, 0);
    cudaStreamWaitEvent(side, evFork, 0);

    const int DD = D_ * D_;
    const int DF = D_ * F_;

    // ---- side stream: weight cvts (critical ones first), then locals chain ----
    launch_cvtp(Wo, two, D_, D_, side);
    launch_cvtp(Wo + DD, two + DD / 2, D_, D_, side);
    launch_cvtp(W1, tw1, D_, F_, side);
    launch_cvtp(W1 + DF, tw1 + DF / 2, D_, F_, side);
    launch_cvtp(W2, tw2, F_, D_, side);
    launch_cvtp(W2 + DF, tw2 + DF / 2, F_, D_, side);
    cvtwp_qkv_kernel<<<((D_ / 2) * (D_ / 4) + 255) / 256, 256, 0, side>>>(
        (const float4*)(Wq + DD), (const float4*)(Wk + DD), (const float4*)(Wv + DD),
        twqkv + (size_t)3 * DD / 2);
    cudaEventRecord(evCvt, side);
    launch_cvtp(Wf1, twf1, D_, F_, side);
    launch_cvtp(Wf2, twf2, F_, D_, side);
    launch_cvtp(Wb, twb, D_, M_, side);
    launch_cvtp(Wm, twm, M_, D_, side);
    gather_fused_kernel<<<RL_, 256, 0, side>>>(x, xs, hxs);
    launch_gemm(hxs, twb, bb, nullptr, hmid, RL_, M_, D_, false, OUT_F16, side);
    launch_gemm(hmid, twm, bm, mo, nullptr, RL_, D_, M_, false, OUT_F32, side);
    ln_kernel<false><<<RL_, 256, 0, side>>>(xs, mo, ln1s, ln1b, y24, nullptr);
    cudaEventRecord(evJoin, side);

    // ---- main stream ----
    cvtwp_qkv_kernel<<<((D_ / 2) * (D_ / 4) + 255) / 256, 256>>>(
        (const float4*)Wq, (const float4*)Wk, (const float4*)Wv, twqkv);
    pack_bqkv_kernel<<<(L_ * 3 * D_ + 255) / 256, 256>>>(bq, bk, bv, bqkv);
    copyx_kernel<<<N_ * D_ / 4 / 256, 256>>>((const float4*)x, (float4*)g,
                                             (uint32_t*)hg, N_ * D_ / 4);

    for (int i = 0; i < L_; i++) {
        launch_gemm(hg, twqkv + (size_t)i * 3 * DD / 2, bqkv + i * 3 * D_,
                    nullptr, hqkv, N_, 3 * D_, D_, false, OUT_F16, 0);
        attn_f16_kernel<<<dim3(B_ * H_, S_ / 64), 256, AT_BYTES2>>>((const uint32_t*)hqkv, hao);
        if (i == 0) cudaStreamWaitEvent(0, evCvt, 0);
        launch_gemm(hao, two + (size_t)i * DD / 2, bo + i * D_, q, nullptr,
                    N_, D_, D_, false, OUT_F32, 0);
        ln_kernel<true><<<N_, 256>>>(g, q, n1s + i * D_, n1b + i * D_, g, hg);
        launch_gemm(hg, tw1 + (size_t)i * DF / 2, b1 + i * F_, nullptr, hff,
                    N_, F_, D_, true, OUT_F16, 0);
        launch_gemm(hff, tw2 + (size_t)i * DF / 2, b2 + i * D_, q, nullptr,
                    N_, D_, F_, false, OUT_F32, 0);
        ln_kernel<true><<<N_, 256>>>(g, q, n2s + i * D_, n2b + i * D_, g, hg);
    }

    cudaStreamWaitEvent(0, evJoin, 0);
    combine_ln2_kernel<<<N_, 256>>>(g, y24, x, ln2s, ln2b, h, hos);
    launch_gemm(hos, twf1, bf1, nullptr, hff, N_, F_, D_, true, OUT_F16, 0);
    launch_gemm(hff, twf2, bf2, q, nullptr, N_, D_, F_, false, OUT_F32, 0);
    ln_kernel<false><<<N_, 256>>>(h, q, ln3s, ln3b, out, nullptr);
}